// round 13
// baseline (speedup 1.0000x reference)
#include <cuda_runtime.h>
#include <cuda_fp16.h>
#include <cstdint>

#define T_STEPS 300
#define BATCH   256
#define NIN     128
#define NH      512
#define NOUT    3
#define DTSEC   0.01f
#define ALPHA_N 0.2f

#define Y_SIZE (BATCH * T_STEPS * NOUT)
#define TS_PAD 304

// ---------------- device scratch (static, allocation-free) ----------------
__device__ float     g_drive[(size_t)T_STEPS * BATCH * NH];   // 157 MB
__device__ uint32_t  g_wrnnp[(NH / 2) * NH];                  // packed half2 (k-pair x h)
__device__ uint32_t  g_winp[(NIN / 2) * NH];
__device__ float     g_wout[NH * NOUT];
__device__ __half    g_rpost[2 * BATCH * NH];                 // double-buffered activations
__device__ __half    g_xh[(size_t)BATCH * T_STEPS * NH];      // fp16 x_seq copy for y (78 MB)
__device__ float     g_yraw[(size_t)T_STEPS * BATCH * NOUT];
__device__ unsigned  g_flag[16 * 8 * TS_PAD];                 // per (group, slice, step)

// ---------------- prep -----------------------------------------------------
__global__ void prep_kernel(const float* __restrict__ w_in, const float* __restrict__ w_in_mask,
                            const float* __restrict__ w_rnn_base, const float* __restrict__ conn,
                            const float* __restrict__ ei, const float* __restrict__ w_out,
                            const float* __restrict__ w_out_mask)
{
    int tid = blockIdx.x * blockDim.x + threadIdx.x;
    int nth = gridDim.x * blockDim.x;

    for (int i = tid; i < (NH / 2) * NH; i += nth) {
        int p = i >> 9, h = i & (NH - 1);
        int k0 = 2 * p, k1 = 2 * p + 1;
        float s0 = ei[k0 * NH + k0];
        float s1 = ei[k1 * NH + k1];
        float v0 = fmaxf(w_rnn_base[k0 * NH + h] * conn[k0 * NH + h], 0.f) * s0;
        float v1 = fmaxf(w_rnn_base[k1 * NH + h] * conn[k1 * NH + h], 0.f) * s1;
        __half2 hv = __floats2half2_rn(v0, v1);
        g_wrnnp[i] = *reinterpret_cast<uint32_t*>(&hv);
    }
    for (int i = tid; i < (NIN / 2) * NH; i += nth) {
        int p = i >> 9, h = i & (NH - 1);
        float v0 = w_in[(2 * p) * NH + h] * w_in_mask[(2 * p) * NH + h];
        float v1 = w_in[(2 * p + 1) * NH + h] * w_in_mask[(2 * p + 1) * NH + h];
        __half2 hv = __floats2half2_rn(v0, v1);
        g_winp[i] = *reinterpret_cast<uint32_t*>(&hv);
    }
    for (int i = tid; i < NH * NOUT; i += nth)
        g_wout[i] = fmaxf(w_out[i] * w_out_mask[i], 0.f);
    for (int i = tid; i < 16 * 8 * TS_PAD; i += nth)
        g_flag[i] = 0u;
}

// ---------------- drive GEMM: drive = 0.2*(inp@w_in_eff + b_rnn) + noise ---
__global__ void __launch_bounds__(256) drive_gemm(const float* __restrict__ inp,
                                                  const float* __restrict__ noise,
                                                  const float* __restrict__ b_rnn)
{
    __shared__ __half   a_s[64 * 136];
    __shared__ uint32_t b_s[64 * 68];

    int row0 = blockIdx.x * 64;
    int n0   = blockIdx.y * 64;
    int tid  = threadIdx.x;

    #pragma unroll
    for (int j = 0; j < 32; j++) {
        int idx = tid + j * 256;
        int i = idx >> 7, k = idx & 127;
        a_s[i * 136 + k] = __float2half_rn(inp[(size_t)(row0 + i) * NIN + k]);
    }
    #pragma unroll
    for (int j = 0; j < 16; j++) {
        int idx = tid + j * 256;
        int p = idx >> 6, c = idx & 63;
        b_s[p * 68 + c] = g_winp[p * NH + n0 + c];
    }
    __syncthreads();

    int w = tid >> 5, lane = tid & 31;
    int g = lane >> 2, t = lane & 3;
    int m0 = (w & 3) * 16;
    int nw = (w >> 2) * 32;

    float acc[4][4] = {};
    #pragma unroll
    for (int kk = 0; kk < 8; kk++) {
        int k0 = kk * 16;
        uint32_t a0 = *reinterpret_cast<const uint32_t*>(&a_s[(m0 + g) * 136 + k0 + 2 * t]);
        uint32_t a1 = *reinterpret_cast<const uint32_t*>(&a_s[(m0 + g + 8) * 136 + k0 + 2 * t]);
        uint32_t a2 = *reinterpret_cast<const uint32_t*>(&a_s[(m0 + g) * 136 + k0 + 8 + 2 * t]);
        uint32_t a3 = *reinterpret_cast<const uint32_t*>(&a_s[(m0 + g + 8) * 136 + k0 + 8 + 2 * t]);
        #pragma unroll
        for (int s = 0; s < 4; s++) {
            int col = nw + 8 * s + g;
            uint32_t b0 = b_s[(kk * 8 + t) * 68 + col];
            uint32_t b1 = b_s[(kk * 8 + t + 4) * 68 + col];
            asm volatile("mma.sync.aligned.m16n8k16.row.col.f32.f16.f16.f32 "
                         "{%0,%1,%2,%3}, {%4,%5,%6,%7}, {%8,%9}, {%0,%1,%2,%3};"
                         : "+f"(acc[s][0]), "+f"(acc[s][1]), "+f"(acc[s][2]), "+f"(acc[s][3])
                         : "r"(a0), "r"(a1), "r"(a2), "r"(a3), "r"(b0), "r"(b1));
        }
    }

    #pragma unroll
    for (int s = 0; s < 4; s++) {
        int gc  = n0 + nw + 8 * s + 2 * t;
        float br0 = b_rnn[gc], br1 = b_rnn[gc + 1];
        int r0 = row0 + m0 + g;
        int r1 = r0 + 8;
        float2 nz0 = *reinterpret_cast<const float2*>(&noise[(size_t)r0 * NH + gc]);
        float2 nz1 = *reinterpret_cast<const float2*>(&noise[(size_t)r1 * NH + gc]);
        float2 d0, d1;
        d0.x = ALPHA_N * (acc[s][0] + br0) + nz0.x;
        d0.y = ALPHA_N * (acc[s][1] + br1) + nz0.y;
        d1.x = ALPHA_N * (acc[s][2] + br0) + nz1.x;
        d1.y = ALPHA_N * (acc[s][3] + br1) + nz1.y;
        *reinterpret_cast<float2*>(&g_drive[(size_t)r0 * NH + gc]) = d0;
        *reinterpret_cast<float2*>(&g_drive[(size_t)r1 * NH + gc]) = d1;
    }
}

// ---------------- persistent step kernel -----------------------------------
// 128 CTAs = 16 b-groups x 8 h-slices. Warp (kh=w>>1, nh=w&1) computes a
// partial C[16x32] over k in [128kh, 128kh+128) (slices 2kh, 2kh+1, whose
// flags lanes 0/16 poll). A-fragments pulled directly L2->registers. 4-way
// reduce combines k-partials (half the smem traffic of the 8-way split).
__global__ void __launch_bounds__(256, 1) step_kernel(
    const float* __restrict__ x_init, const float* __restrict__ sx_init,
    const float* __restrict__ su_init,
    const float* __restrict__ a_std, const float* __restrict__ a_stf,
    const float* __restrict__ Uv, const float* __restrict__ dynv,
    float* __restrict__ out_x)
{
    __shared__ float red[8][16][36];     // per-warp partial C[16x32], padded

    int cta   = blockIdx.x;
    int grp   = cta >> 3;
    int slice = cta & 7;
    int b0 = grp * 16;
    int h0 = slice * 64;
    int tid = threadIdx.x;
    int w = tid >> 5, lane = tid & 31;
    int g = lane >> 2, t = lane & 3;
    int kh = w >> 1;        // k-range [128kh, 128kh+128)
    int nh = w & 1;         // n-range [32nh, 32nh+32) within slice

    // ---- persistent B fragments: k-range x n-range of this warp ----
    // global k-pair p = 64kh + 8kk + t (+4); col = h0 + 32nh + 8j + g
    uint32_t breg0[32], breg1[32];
    #pragma unroll
    for (int kk = 0; kk < 8; kk++)
        #pragma unroll
        for (int j = 0; j < 4; j++) {
            int col = h0 + 32 * nh + 8 * j + g;
            breg0[kk * 4 + j] = g_wrnnp[(size_t)(64 * kh + 8 * kk + t) * NH + col];
            breg1[kk * 4 + j] = g_wrnnp[(size_t)(64 * kh + 8 * kk + t + 4) * NH + col];
        }

    int hb  = h0 + 8 * w + 2 * t;
    int br0 = b0 + g, br1 = b0 + g + 8;

    float as0 = a_std[hb], as1 = a_std[hb + 1];
    float af0_ = a_stf[hb], af1_ = a_stf[hb + 1];
    float U0  = Uv[hb],    U1  = Uv[hb + 1];
    float dy0 = dynv[hb],  dy1 = dynv[hb + 1];

    float x0 = x_init[br0 * NH + hb],   x1 = x_init[br0 * NH + hb + 1];
    float x2 = x_init[br1 * NH + hb],   x3 = x_init[br1 * NH + hb + 1];
    float sx0 = sx_init[br0 * NH + hb], sx1 = sx_init[br0 * NH + hb + 1];
    float sx2 = sx_init[br1 * NH + hb], sx3 = sx_init[br1 * NH + hb + 1];
    float su0 = su_init[br0 * NH + hb], su1 = su_init[br0 * NH + hb + 1];
    float su2 = su_init[br1 * NH + hb], su3 = su_init[br1 * NH + hb + 1];

    __half2* rgl = reinterpret_cast<__half2*>(g_rpost);
    __half2* xh2 = reinterpret_cast<__half2*>(g_xh);

    unsigned* my_flag = g_flag + (grp * 8 + slice) * TS_PAD;          // producer
    int s0p = 2 * kh, s1p = 2 * kh + 1;                               // consumed slices
    unsigned* f0 = g_flag + (grp * 8 + s0p) * TS_PAD;
    unsigned* f1 = g_flag + (grp * 8 + s1p) * TS_PAD;

    for (int ts = 0; ts < T_STEPS; ts++) {
        // ---- prefetch drive early (consumed after MMA) ----
        float2 d0 = *reinterpret_cast<const float2*>(&g_drive[((size_t)ts * BATCH + br0) * NH + hb]);
        float2 d1 = *reinterpret_cast<const float2*>(&g_drive[((size_t)ts * BATCH + br1) * NH + hb]);

        // ---- phase 1: STP update + x_post + rpost ----
        float xp0, xp1, xp2, xp3;
        {
            float r, sxn, sun;
            r = fmaxf(x0, 0.f);
            sxn = sx0 + (as0 * (1.f - sx0) - DTSEC * su0 * sx0 * r) * dy0;
            sun = su0 + (af0_ * (U0 - su0) + DTSEC * U0 * (1.f - su0) * r) * dy0;
            sx0 = fminf(fmaxf(sxn, 0.f), 1.f); su0 = fminf(fmaxf(sun, 0.f), 1.f);
            xp0 = su0 * sx0 * x0;

            r = fmaxf(x1, 0.f);
            sxn = sx1 + (as1 * (1.f - sx1) - DTSEC * su1 * sx1 * r) * dy1;
            sun = su1 + (af1_ * (U1 - su1) + DTSEC * U1 * (1.f - su1) * r) * dy1;
            sx1 = fminf(fmaxf(sxn, 0.f), 1.f); su1 = fminf(fmaxf(sun, 0.f), 1.f);
            xp1 = su1 * sx1 * x1;

            r = fmaxf(x2, 0.f);
            sxn = sx2 + (as0 * (1.f - sx2) - DTSEC * su2 * sx2 * r) * dy0;
            sun = su2 + (af0_ * (U0 - su2) + DTSEC * U0 * (1.f - su2) * r) * dy0;
            sx2 = fminf(fmaxf(sxn, 0.f), 1.f); su2 = fminf(fmaxf(sun, 0.f), 1.f);
            xp2 = su2 * sx2 * x2;

            r = fmaxf(x3, 0.f);
            sxn = sx3 + (as1 * (1.f - sx3) - DTSEC * su3 * sx3 * r) * dy1;
            sun = su3 + (af1_ * (U1 - su3) + DTSEC * U1 * (1.f - su3) * r) * dy1;
            sx3 = fminf(fmaxf(sxn, 0.f), 1.f); su3 = fminf(fmaxf(sun, 0.f), 1.f);
            xp3 = su3 * sx3 * x3;
        }
        int buf = ts & 1;
        rgl[(buf * BATCH * NH + br0 * NH + hb) >> 1] =
            __floats2half2_rn(fmaxf(xp0, 0.f), fmaxf(xp1, 0.f));
        rgl[(buf * BATCH * NH + br1 * NH + hb) >> 1] =
            __floats2half2_rn(fmaxf(xp2, 0.f), fmaxf(xp3, 0.f));

        // ---- publish: single-writer release flag (no RMW) ----
        // Sync also guards red[] reuse (prev step's reduce loads done).
        __syncthreads();
        if (tid == 0)
            asm volatile("st.release.gpu.global.u32 [%0], %1;"
                         :: "l"(my_flag + ts), "r"(1u) : "memory");

        // ---- wait for this warp's two k-slices (parallel discovery) ----
        if (lane == 0 && s0p != slice) {
            unsigned v;
            do {
                asm volatile("ld.acquire.gpu.global.u32 %0, [%1];"
                             : "=r"(v) : "l"(f0 + ts) : "memory");
            } while (!v);
        }
        if (lane == 16 && s1p != slice) {
            unsigned v;
            do {
                asm volatile("ld.acquire.gpu.global.u32 %0, [%1];"
                             : "=r"(v) : "l"(f1 + ts) : "memory");
            } while (!v);
        }
        __syncwarp();

        // ---- pull A-fragments for k-range [128kh, 128kh+128) ----
        uint32_t af[32];
        {
            const __half* Ap = g_rpost + (size_t)buf * BATCH * NH
                               + (size_t)(b0 + g) * NH + 128 * kh + 2 * t;
            #pragma unroll
            for (int kk = 0; kk < 8; kk++) {
                asm volatile("ld.global.cg.b32 %0, [%1];"
                             : "=r"(af[kk * 4 + 0]) : "l"(Ap + 16 * kk));
                asm volatile("ld.global.cg.b32 %0, [%1];"
                             : "=r"(af[kk * 4 + 1]) : "l"(Ap + 8 * NH + 16 * kk));
                asm volatile("ld.global.cg.b32 %0, [%1];"
                             : "=r"(af[kk * 4 + 2]) : "l"(Ap + 16 * kk + 8));
                asm volatile("ld.global.cg.b32 %0, [%1];"
                             : "=r"(af[kk * 4 + 3]) : "l"(Ap + 8 * NH + 16 * kk + 8));
            }
        }

        // ---- partial mma: C[16x32] over this warp's k-range; 4 chains ----
        float acc[4][4] = {};
        #pragma unroll
        for (int kk = 0; kk < 8; kk++)
            #pragma unroll
            for (int j = 0; j < 4; j++)
                asm volatile("mma.sync.aligned.m16n8k16.row.col.f32.f16.f16.f32 "
                             "{%0,%1,%2,%3}, {%4,%5,%6,%7}, {%8,%9}, {%0,%1,%2,%3};"
                             : "+f"(acc[j][0]), "+f"(acc[j][1]), "+f"(acc[j][2]), "+f"(acc[j][3])
                             : "r"(af[kk * 4 + 0]), "r"(af[kk * 4 + 1]),
                               "r"(af[kk * 4 + 2]), "r"(af[kk * 4 + 3]),
                               "r"(breg0[kk * 4 + j]), "r"(breg1[kk * 4 + j]));

        // ---- store partials ----
        #pragma unroll
        for (int j = 0; j < 4; j++) {
            *reinterpret_cast<float2*>(&red[w][g][8 * j + 2 * t]) =
                make_float2(acc[j][0], acc[j][1]);
            *reinterpret_cast<float2*>(&red[w][g + 8][8 * j + 2 * t]) =
                make_float2(acc[j][2], acc[j][3]);
        }
        __syncthreads();

        // ---- reduce: sum 4 k-partials for this thread's owned outputs ----
        int nho = w >> 2;                  // which 32-col half owns hb
        int cl  = 8 * (w & 3) + 2 * t;     // local col within that half
        float s0 = 0.f, s1 = 0.f, s2 = 0.f, s3 = 0.f;
        #pragma unroll
        for (int u = 0; u < 4; u++) {
            int pw = 2 * u + nho;
            float2 p = *reinterpret_cast<const float2*>(&red[pw][g][cl]);
            float2 q = *reinterpret_cast<const float2*>(&red[pw][g + 8][cl]);
            s0 += p.x; s1 += p.y; s2 += q.x; s3 += q.y;
        }

        // ---- epilogue: x_new; store x_seq (f32 out + fp16 copy for y) ----
        x0 = (1.f - ALPHA_N) * xp0 + ALPHA_N * s0 + d0.x;
        x1 = (1.f - ALPHA_N) * xp1 + ALPHA_N * s1 + d0.y;
        x2 = (1.f - ALPHA_N) * xp2 + ALPHA_N * s2 + d1.x;
        x3 = (1.f - ALPHA_N) * xp3 + ALPHA_N * s3 + d1.y;
        size_t o0 = ((size_t)br0 * T_STEPS + ts) * NH + hb;
        size_t o1 = ((size_t)br1 * T_STEPS + ts) * NH + hb;
        *reinterpret_cast<float2*>(&out_x[o0]) = make_float2(x0, x1);
        *reinterpret_cast<float2*>(&out_x[o1]) = make_float2(x2, x3);
        xh2[o0 >> 1] = __floats2half2_rn(x0, x1);
        xh2[o1 >> 1] = __floats2half2_rn(x2, x3);
    }
}

// ---------------- y = relu(x) @ w_out_eff + b_out (fp16 input) -------------
__global__ void __launch_bounds__(256) y_kernel(const float* __restrict__ b_out)
{
    __shared__ float wsh[NH * NOUT];
    for (int i = threadIdx.x; i < NH * NOUT; i += 256) wsh[i] = g_wout[i];
    __syncthreads();

    int w = threadIdx.x >> 5, lane = threadIdx.x & 31;
    int row = blockIdx.x * 8 + w;           // t*256 + b
    int t = row >> 8;
    int b = row & 255;
    const __half2* xr = reinterpret_cast<const __half2*>(g_xh)
                        + ((((size_t)b * T_STEPS + t) * NH) >> 1);

    float a0 = 0.f, a1 = 0.f, a2 = 0.f;
    #pragma unroll
    for (int k = 0; k < 8; k++) {
        __half2 hv = xr[lane + 32 * k];
        float2 rf = __half22float2(hv);
        float r0 = fmaxf(rf.x, 0.f), r1 = fmaxf(rf.y, 0.f);
        int h = 2 * (lane + 32 * k);
        a0 += r0 * wsh[h * 3 + 0] + r1 * wsh[h * 3 + 3];
        a1 += r0 * wsh[h * 3 + 1] + r1 * wsh[h * 3 + 4];
        a2 += r0 * wsh[h * 3 + 2] + r1 * wsh[h * 3 + 5];
    }
    #pragma unroll
    for (int off = 16; off > 0; off >>= 1) {
        a0 += __shfl_xor_sync(0xffffffffu, a0, off);
        a1 += __shfl_xor_sync(0xffffffffu, a1, off);
        a2 += __shfl_xor_sync(0xffffffffu, a2, off);
    }
    if (lane == 0) {
        size_t base = ((size_t)t * BATCH + b) * NOUT;
        g_yraw[base + 0] = a0 + b_out[0];
        g_yraw[base + 1] = a1 + b_out[1];
        g_yraw[base + 2] = a2 + b_out[2];
    }
}

// ---------------- softmax over batch axis ----------------------------------
__global__ void __launch_bounds__(256) softmax_kernel(float* __restrict__ out_y)
{
    __shared__ float red[256];
    int t = blockIdx.x;
    int b = threadIdx.x;
    float v[NOUT], e[NOUT];
    #pragma unroll
    for (int o = 0; o < NOUT; o++)
        v[o] = g_yraw[((size_t)t * BATCH + b) * NOUT + o];

    #pragma unroll
    for (int o = 0; o < NOUT; o++) {
        red[b] = v[o];
        __syncthreads();
        for (int s = 128; s > 0; s >>= 1) {
            if (b < s) red[b] = fmaxf(red[b], red[b + s]);
            __syncthreads();
        }
        float mx = red[0];
        __syncthreads();
        e[o] = expf(v[o] - mx);
        red[b] = e[o];
        __syncthreads();
        for (int s = 128; s > 0; s >>= 1) {
            if (b < s) red[b] += red[b + s];
            __syncthreads();
        }
        float sm = red[0];
        __syncthreads();
        out_y[((size_t)b * T_STEPS + t) * NOUT + o] = e[o] / sm;
    }
}

// ---------------- launch ----------------------------------------------------
extern "C" void kernel_launch(void* const* d_in, const int* in_sizes, int n_in,
                              void* d_out, int out_size)
{
    const float* input_data = (const float*)d_in[0];
    const float* noise      = (const float*)d_in[1];
    const float* x_init     = (const float*)d_in[2];
    const float* syn_x_init = (const float*)d_in[3];
    const float* syn_u_init = (const float*)d_in[4];
    const float* w_in       = (const float*)d_in[5];
    const float* w_in_mask  = (const float*)d_in[6];
    const float* w_rnn_base = (const float*)d_in[7];
    const float* conn_mask  = (const float*)d_in[8];
    const float* ei_matrix  = (const float*)d_in[9];
    const float* b_rnn      = (const float*)d_in[10];
    const float* w_out      = (const float*)d_in[11];
    const float* w_out_mask = (const float*)d_in[12];
    const float* b_out      = (const float*)d_in[13];
    const float* a_std      = (const float*)d_in[14];
    const float* a_stf      = (const float*)d_in[15];
    const float* Uv         = (const float*)d_in[16];
    const float* dynv       = (const float*)d_in[17];

    float* out   = (float*)d_out;
    float* out_y = out;
    float* out_x = out + Y_SIZE;

    prep_kernel<<<148, 256>>>(w_in, w_in_mask, w_rnn_base, conn_mask, ei_matrix,
                              w_out, w_out_mask);
    dim3 dgrid(76800 / 64, NH / 64);
    drive_gemm<<<dgrid, 256>>>(input_data, noise, b_rnn);
    step_kernel<<<128, 256>>>(x_init, syn_x_init, syn_u_init,
                              a_std, a_stf, Uv, dynv, out_x);
    y_kernel<<<76800 / 8, 256>>>(b_out);
    softmax_kernel<<<T_STEPS, 256>>>(out_y);
}

// round 14
// speedup vs baseline: 1.2476x; 1.2476x over previous
#include <cuda_runtime.h>
#include <cuda_fp16.h>
#include <cstdint>

#define T_STEPS 300
#define BATCH   256
#define NIN     128
#define NH      512
#define NOUT    3
#define DTSEC   0.01f
#define ALPHA_N 0.2f

#define Y_SIZE (BATCH * T_STEPS * NOUT)
#define TS_PAD 304

// ---------------- device scratch (static, allocation-free) ----------------
__device__ __half    g_driveh[(size_t)T_STEPS * BATCH * NH];  // 78 MB: 0.2*(inp@Win+b)
__device__ uint32_t  g_wrnnp[(NH / 2) * NH];                  // packed half2 (k-pair x h)
__device__ uint32_t  g_winp[(NIN / 2) * NH];
__device__ float     g_wout[NH * NOUT];
__device__ __half    g_rpost[2 * BATCH * NH];                 // double-buffered activations
__device__ __half    g_xh[(size_t)BATCH * T_STEPS * NH];      // fp16 x_seq copy for y (78 MB)
__device__ float     g_yraw[(size_t)T_STEPS * BATCH * NOUT];
__device__ unsigned  g_flag[16 * 8 * TS_PAD];                 // per (group, slice, step)

// ---------------- prep -----------------------------------------------------
__global__ void prep_kernel(const float* __restrict__ w_in, const float* __restrict__ w_in_mask,
                            const float* __restrict__ w_rnn_base, const float* __restrict__ conn,
                            const float* __restrict__ ei, const float* __restrict__ w_out,
                            const float* __restrict__ w_out_mask)
{
    int tid = blockIdx.x * blockDim.x + threadIdx.x;
    int nth = gridDim.x * blockDim.x;

    for (int i = tid; i < (NH / 2) * NH; i += nth) {
        int p = i >> 9, h = i & (NH - 1);
        int k0 = 2 * p, k1 = 2 * p + 1;
        float s0 = ei[k0 * NH + k0];
        float s1 = ei[k1 * NH + k1];
        float v0 = fmaxf(w_rnn_base[k0 * NH + h] * conn[k0 * NH + h], 0.f) * s0;
        float v1 = fmaxf(w_rnn_base[k1 * NH + h] * conn[k1 * NH + h], 0.f) * s1;
        __half2 hv = __floats2half2_rn(v0, v1);
        g_wrnnp[i] = *reinterpret_cast<uint32_t*>(&hv);
    }
    for (int i = tid; i < (NIN / 2) * NH; i += nth) {
        int p = i >> 9, h = i & (NH - 1);
        float v0 = w_in[(2 * p) * NH + h] * w_in_mask[(2 * p) * NH + h];
        float v1 = w_in[(2 * p + 1) * NH + h] * w_in_mask[(2 * p + 1) * NH + h];
        __half2 hv = __floats2half2_rn(v0, v1);
        g_winp[i] = *reinterpret_cast<uint32_t*>(&hv);
    }
    for (int i = tid; i < NH * NOUT; i += nth)
        g_wout[i] = fmaxf(w_out[i] * w_out_mask[i], 0.f);
    for (int i = tid; i < 16 * 8 * TS_PAD; i += nth)
        g_flag[i] = 0u;
}

// ---------------- drive GEMM: drive' = fp16(0.2*(inp@w_in_eff + b_rnn)) ----
__global__ void __launch_bounds__(256) drive_gemm(const float* __restrict__ inp,
                                                  const float* __restrict__ b_rnn)
{
    __shared__ __half   a_s[64 * 136];
    __shared__ uint32_t b_s[64 * 68];

    int row0 = blockIdx.x * 64;
    int n0   = blockIdx.y * 64;
    int tid  = threadIdx.x;

    #pragma unroll
    for (int j = 0; j < 32; j++) {
        int idx = tid + j * 256;
        int i = idx >> 7, k = idx & 127;
        a_s[i * 136 + k] = __float2half_rn(inp[(size_t)(row0 + i) * NIN + k]);
    }
    #pragma unroll
    for (int j = 0; j < 16; j++) {
        int idx = tid + j * 256;
        int p = idx >> 6, c = idx & 63;
        b_s[p * 68 + c] = g_winp[p * NH + n0 + c];
    }
    __syncthreads();

    int w = tid >> 5, lane = tid & 31;
    int g = lane >> 2, t = lane & 3;
    int m0 = (w & 3) * 16;
    int nw = (w >> 2) * 32;

    float acc[4][4] = {};
    #pragma unroll
    for (int kk = 0; kk < 8; kk++) {
        int k0 = kk * 16;
        uint32_t a0 = *reinterpret_cast<const uint32_t*>(&a_s[(m0 + g) * 136 + k0 + 2 * t]);
        uint32_t a1 = *reinterpret_cast<const uint32_t*>(&a_s[(m0 + g + 8) * 136 + k0 + 2 * t]);
        uint32_t a2 = *reinterpret_cast<const uint32_t*>(&a_s[(m0 + g) * 136 + k0 + 8 + 2 * t]);
        uint32_t a3 = *reinterpret_cast<const uint32_t*>(&a_s[(m0 + g + 8) * 136 + k0 + 8 + 2 * t]);
        #pragma unroll
        for (int s = 0; s < 4; s++) {
            int col = nw + 8 * s + g;
            uint32_t b0 = b_s[(kk * 8 + t) * 68 + col];
            uint32_t b1 = b_s[(kk * 8 + t + 4) * 68 + col];
            asm volatile("mma.sync.aligned.m16n8k16.row.col.f32.f16.f16.f32 "
                         "{%0,%1,%2,%3}, {%4,%5,%6,%7}, {%8,%9}, {%0,%1,%2,%3};"
                         : "+f"(acc[s][0]), "+f"(acc[s][1]), "+f"(acc[s][2]), "+f"(acc[s][3])
                         : "r"(a0), "r"(a1), "r"(a2), "r"(a3), "r"(b0), "r"(b1));
        }
    }

    __half2* dh = reinterpret_cast<__half2*>(g_driveh);
    #pragma unroll
    for (int s = 0; s < 4; s++) {
        int gc  = n0 + nw + 8 * s + 2 * t;
        float br0 = b_rnn[gc], br1 = b_rnn[gc + 1];
        int r0 = row0 + m0 + g;
        int r1 = r0 + 8;
        dh[((size_t)r0 * NH + gc) >> 1] =
            __floats2half2_rn(ALPHA_N * (acc[s][0] + br0), ALPHA_N * (acc[s][1] + br1));
        dh[((size_t)r1 * NH + gc) >> 1] =
            __floats2half2_rn(ALPHA_N * (acc[s][2] + br0), ALPHA_N * (acc[s][3] + br1));
    }
}

// ---------------- persistent step kernel (R11 layout) -----------------------
// 128 CTAs = 16 b-groups x 8 h-slices. K-split per warp: warp w computes
// partial C over k-range [64w, 64w+64) (= slice w, whose flag it polls),
// loading A-fragments DIRECTLY from L2 into registers. Flat smem reduction
// combines the 8 k-partials.
__global__ void __launch_bounds__(256, 1) step_kernel(
    const float* __restrict__ noise,
    const float* __restrict__ x_init, const float* __restrict__ sx_init,
    const float* __restrict__ su_init,
    const float* __restrict__ a_std, const float* __restrict__ a_stf,
    const float* __restrict__ Uv, const float* __restrict__ dynv,
    float* __restrict__ out_x)
{
    __shared__ float red[8][16][72];     // per-warp partial C, padded rows

    int cta   = blockIdx.x;
    int grp   = cta >> 3;
    int slice = cta & 7;
    int b0 = grp * 16;
    int h0 = slice * 64;
    int tid = threadIdx.x;
    int w = tid >> 5, lane = tid & 31;
    int g = lane >> 2, t = lane & 3;

    // ---- persistent B fragments: warp w's k-range x this CTA's 64 cols ----
    uint32_t breg0[32], breg1[32];
    #pragma unroll
    for (int kk = 0; kk < 4; kk++)
        #pragma unroll
        for (int j = 0; j < 8; j++) {
            int col = h0 + 8 * j + g;
            breg0[kk * 8 + j] = g_wrnnp[(size_t)(32 * w + 8 * kk + t) * NH + col];
            breg1[kk * 8 + j] = g_wrnnp[(size_t)(32 * w + 8 * kk + t + 4) * NH + col];
        }

    int hb  = h0 + 8 * w + 2 * t;
    int br0 = b0 + g, br1 = b0 + g + 8;

    float as0 = a_std[hb], as1 = a_std[hb + 1];
    float af0 = a_stf[hb], af1 = a_stf[hb + 1];
    float U0  = Uv[hb],    U1  = Uv[hb + 1];
    float dy0 = dynv[hb],  dy1 = dynv[hb + 1];

    float x0 = x_init[br0 * NH + hb],   x1 = x_init[br0 * NH + hb + 1];
    float x2 = x_init[br1 * NH + hb],   x3 = x_init[br1 * NH + hb + 1];
    float sx0 = sx_init[br0 * NH + hb], sx1 = sx_init[br0 * NH + hb + 1];
    float sx2 = sx_init[br1 * NH + hb], sx3 = sx_init[br1 * NH + hb + 1];
    float su0 = su_init[br0 * NH + hb], su1 = su_init[br0 * NH + hb + 1];
    float su2 = su_init[br1 * NH + hb], su3 = su_init[br1 * NH + hb + 1];

    __half2* rgl = reinterpret_cast<__half2*>(g_rpost);
    __half2* xh2 = reinterpret_cast<__half2*>(g_xh);
    const __half2* dh = reinterpret_cast<const __half2*>(g_driveh);

    unsigned* my_flag   = g_flag + (grp * 8 + slice) * TS_PAD;   // producer stream
    unsigned* poll_flag = g_flag + (grp * 8 + w) * TS_PAD;       // warp w consumes slice w

    for (int ts = 0; ts < T_STEPS; ts++) {
        // ---- prefetch drive' (fp16) + noise (f32) early ----
        size_t dbase0 = ((size_t)ts * BATCH + br0) * NH + hb;
        size_t dbase1 = ((size_t)ts * BATCH + br1) * NH + hb;
        __half2 dr0 = dh[dbase0 >> 1];
        __half2 dr1 = dh[dbase1 >> 1];
        float2 nz0 = *reinterpret_cast<const float2*>(&noise[dbase0]);
        float2 nz1 = *reinterpret_cast<const float2*>(&noise[dbase1]);

        // ---- phase 1: STP update + x_post + rpost ----
        float xp0, xp1, xp2, xp3;
        {
            float r, sxn, sun;
            r = fmaxf(x0, 0.f);
            sxn = sx0 + (as0 * (1.f - sx0) - DTSEC * su0 * sx0 * r) * dy0;
            sun = su0 + (af0 * (U0 - su0) + DTSEC * U0 * (1.f - su0) * r) * dy0;
            sx0 = fminf(fmaxf(sxn, 0.f), 1.f); su0 = fminf(fmaxf(sun, 0.f), 1.f);
            xp0 = su0 * sx0 * x0;

            r = fmaxf(x1, 0.f);
            sxn = sx1 + (as1 * (1.f - sx1) - DTSEC * su1 * sx1 * r) * dy1;
            sun = su1 + (af1 * (U1 - su1) + DTSEC * U1 * (1.f - su1) * r) * dy1;
            sx1 = fminf(fmaxf(sxn, 0.f), 1.f); su1 = fminf(fmaxf(sun, 0.f), 1.f);
            xp1 = su1 * sx1 * x1;

            r = fmaxf(x2, 0.f);
            sxn = sx2 + (as0 * (1.f - sx2) - DTSEC * su2 * sx2 * r) * dy0;
            sun = su2 + (af0 * (U0 - su2) + DTSEC * U0 * (1.f - su2) * r) * dy0;
            sx2 = fminf(fmaxf(sxn, 0.f), 1.f); su2 = fminf(fmaxf(sun, 0.f), 1.f);
            xp2 = su2 * sx2 * x2;

            r = fmaxf(x3, 0.f);
            sxn = sx3 + (as1 * (1.f - sx3) - DTSEC * su3 * sx3 * r) * dy1;
            sun = su3 + (af1 * (U1 - su3) + DTSEC * U1 * (1.f - su3) * r) * dy1;
            sx3 = fminf(fmaxf(sxn, 0.f), 1.f); su3 = fminf(fmaxf(sun, 0.f), 1.f);
            xp3 = su3 * sx3 * x3;
        }
        int buf = ts & 1;
        rgl[(buf * BATCH * NH + br0 * NH + hb) >> 1] =
            __floats2half2_rn(fmaxf(xp0, 0.f), fmaxf(xp1, 0.f));
        rgl[(buf * BATCH * NH + br1 * NH + hb) >> 1] =
            __floats2half2_rn(fmaxf(xp2, 0.f), fmaxf(xp3, 0.f));

        // ---- publish: single-writer release flag (no RMW) ----
        // Sync also guards red[] reuse (prev step's reduce loads done).
        __syncthreads();
        if (tid == 0)
            asm volatile("st.release.gpu.global.u32 [%0], %1;"
                         :: "l"(my_flag + ts), "r"(1u) : "memory");

        // ---- per-warp: wait for slice w, pull A-fragments to registers ----
        if (w != slice && lane == 0) {
            unsigned v;
            do {
                asm volatile("ld.acquire.gpu.global.u32 %0, [%1];"
                             : "=r"(v) : "l"(poll_flag + ts) : "memory");
            } while (!v);
        }
        __syncwarp();

        uint32_t af[16];
        {
            const __half* Ap = g_rpost + (size_t)buf * BATCH * NH
                               + (size_t)(b0 + g) * NH + 64 * w + 2 * t;
            #pragma unroll
            for (int kk = 0; kk < 4; kk++) {
                asm volatile("ld.global.cg.b32 %0, [%1];"
                             : "=r"(af[kk * 4 + 0]) : "l"(Ap + 16 * kk));
                asm volatile("ld.global.cg.b32 %0, [%1];"
                             : "=r"(af[kk * 4 + 1]) : "l"(Ap + 8 * NH + 16 * kk));
                asm volatile("ld.global.cg.b32 %0, [%1];"
                             : "=r"(af[kk * 4 + 2]) : "l"(Ap + 16 * kk + 8));
                asm volatile("ld.global.cg.b32 %0, [%1];"
                             : "=r"(af[kk * 4 + 3]) : "l"(Ap + 8 * NH + 16 * kk + 8));
            }
        }

        // ---- partial mma: C_w[16x64] = rpost[16, k-slice w] @ W[k-slice w, :]
        float acc[8][4] = {};
        #pragma unroll
        for (int kk = 0; kk < 4; kk++)
            #pragma unroll
            for (int j = 0; j < 8; j++)
                asm volatile("mma.sync.aligned.m16n8k16.row.col.f32.f16.f16.f32 "
                             "{%0,%1,%2,%3}, {%4,%5,%6,%7}, {%8,%9}, {%0,%1,%2,%3};"
                             : "+f"(acc[j][0]), "+f"(acc[j][1]), "+f"(acc[j][2]), "+f"(acc[j][3])
                             : "r"(af[kk * 4 + 0]), "r"(af[kk * 4 + 1]),
                               "r"(af[kk * 4 + 2]), "r"(af[kk * 4 + 3]),
                               "r"(breg0[kk * 8 + j]), "r"(breg1[kk * 8 + j]));

        // ---- store partials to smem ----
        #pragma unroll
        for (int j = 0; j < 8; j++) {
            *reinterpret_cast<float2*>(&red[w][g][8 * j + 2 * t]) =
                make_float2(acc[j][0], acc[j][1]);
            *reinterpret_cast<float2*>(&red[w][g + 8][8 * j + 2 * t]) =
                make_float2(acc[j][2], acc[j][3]);
        }
        __syncthreads();

        // ---- reduce: each thread sums its 4 owned outputs over 8 partials ----
        float s0 = 0.f, s1 = 0.f, s2 = 0.f, s3 = 0.f;
        #pragma unroll
        for (int u = 0; u < 8; u++) {
            float2 p = *reinterpret_cast<const float2*>(&red[u][g][8 * w + 2 * t]);
            float2 q = *reinterpret_cast<const float2*>(&red[u][g + 8][8 * w + 2 * t]);
            s0 += p.x; s1 += p.y; s2 += q.x; s3 += q.y;
        }

        // ---- epilogue: x_new = 0.8*x_post + 0.2*acc + drive' + noise ----
        float2 dv0 = __half22float2(dr0);
        float2 dv1 = __half22float2(dr1);
        x0 = (1.f - ALPHA_N) * xp0 + ALPHA_N * s0 + dv0.x + nz0.x;
        x1 = (1.f - ALPHA_N) * xp1 + ALPHA_N * s1 + dv0.y + nz0.y;
        x2 = (1.f - ALPHA_N) * xp2 + ALPHA_N * s2 + dv1.x + nz1.x;
        x3 = (1.f - ALPHA_N) * xp3 + ALPHA_N * s3 + dv1.y + nz1.y;
        size_t o0 = ((size_t)br0 * T_STEPS + ts) * NH + hb;
        size_t o1 = ((size_t)br1 * T_STEPS + ts) * NH + hb;
        *reinterpret_cast<float2*>(&out_x[o0]) = make_float2(x0, x1);
        *reinterpret_cast<float2*>(&out_x[o1]) = make_float2(x2, x3);
        xh2[o0 >> 1] = __floats2half2_rn(x0, x1);
        xh2[o1 >> 1] = __floats2half2_rn(x2, x3);
    }
}

// ---------------- y = relu(x) @ w_out_eff + b_out (fp16 input) -------------
__global__ void __launch_bounds__(256) y_kernel(const float* __restrict__ b_out)
{
    __shared__ float wsh[NH * NOUT];
    for (int i = threadIdx.x; i < NH * NOUT; i += 256) wsh[i] = g_wout[i];
    __syncthreads();

    int w = threadIdx.x >> 5, lane = threadIdx.x & 31;
    int row = blockIdx.x * 8 + w;           // t*256 + b
    int t = row >> 8;
    int b = row & 255;
    const __half2* xr = reinterpret_cast<const __half2*>(g_xh)
                        + ((((size_t)b * T_STEPS + t) * NH) >> 1);

    float a0 = 0.f, a1 = 0.f, a2 = 0.f;
    #pragma unroll
    for (int k = 0; k < 8; k++) {
        __half2 hv = xr[lane + 32 * k];
        float2 rf = __half22float2(hv);
        float r0 = fmaxf(rf.x, 0.f), r1 = fmaxf(rf.y, 0.f);
        int h = 2 * (lane + 32 * k);
        a0 += r0 * wsh[h * 3 + 0] + r1 * wsh[h * 3 + 3];
        a1 += r0 * wsh[h * 3 + 1] + r1 * wsh[h * 3 + 4];
        a2 += r0 * wsh[h * 3 + 2] + r1 * wsh[h * 3 + 5];
    }
    #pragma unroll
    for (int off = 16; off > 0; off >>= 1) {
        a0 += __shfl_xor_sync(0xffffffffu, a0, off);
        a1 += __shfl_xor_sync(0xffffffffu, a1, off);
        a2 += __shfl_xor_sync(0xffffffffu, a2, off);
    }
    if (lane == 0) {
        size_t base = ((size_t)t * BATCH + b) * NOUT;
        g_yraw[base + 0] = a0 + b_out[0];
        g_yraw[base + 1] = a1 + b_out[1];
        g_yraw[base + 2] = a2 + b_out[2];
    }
}

// ---------------- softmax over batch axis ----------------------------------
__global__ void __launch_bounds__(256) softmax_kernel(float* __restrict__ out_y)
{
    __shared__ float red[256];
    int t = blockIdx.x;
    int b = threadIdx.x;
    float v[NOUT], e[NOUT];
    #pragma unroll
    for (int o = 0; o < NOUT; o++)
        v[o] = g_yraw[((size_t)t * BATCH + b) * NOUT + o];

    #pragma unroll
    for (int o = 0; o < NOUT; o++) {
        red[b] = v[o];
        __syncthreads();
        for (int s = 128; s > 0; s >>= 1) {
            if (b < s) red[b] = fmaxf(red[b], red[b + s]);
            __syncthreads();
        }
        float mx = red[0];
        __syncthreads();
        e[o] = expf(v[o] - mx);
        red[b] = e[o];
        __syncthreads();
        for (int s = 128; s > 0; s >>= 1) {
            if (b < s) red[b] += red[b + s];
            __syncthreads();
        }
        float sm = red[0];
        __syncthreads();
        out_y[((size_t)b * T_STEPS + t) * NOUT + o] = e[o] / sm;
    }
}

// ---------------- launch ----------------------------------------------------
extern "C" void kernel_launch(void* const* d_in, const int* in_sizes, int n_in,
                              void* d_out, int out_size)
{
    const float* input_data = (const float*)d_in[0];
    const float* noise      = (const float*)d_in[1];
    const float* x_init     = (const float*)d_in[2];
    const float* syn_x_init = (const float*)d_in[3];
    const float* syn_u_init = (const float*)d_in[4];
    const float* w_in       = (const float*)d_in[5];
    const float* w_in_mask  = (const float*)d_in[6];
    const float* w_rnn_base = (const float*)d_in[7];
    const float* conn_mask  = (const float*)d_in[8];
    const float* ei_matrix  = (const float*)d_in[9];
    const float* b_rnn      = (const float*)d_in[10];
    const float* w_out      = (const float*)d_in[11];
    const float* w_out_mask = (const float*)d_in[12];
    const float* b_out      = (const float*)d_in[13];
    const float* a_std      = (const float*)d_in[14];
    const float* a_stf      = (const float*)d_in[15];
    const float* Uv         = (const float*)d_in[16];
    const float* dynv       = (const float*)d_in[17];

    float* out   = (float*)d_out;
    float* out_y = out;
    float* out_x = out + Y_SIZE;

    prep_kernel<<<148, 256>>>(w_in, w_in_mask, w_rnn_base, conn_mask, ei_matrix,
                              w_out, w_out_mask);
    dim3 dgrid(76800 / 64, NH / 64);
    drive_gemm<<<dgrid, 256>>>(input_data, b_rnn);
    step_kernel<<<128, 256>>>(noise, x_init, syn_x_init, syn_u_init,
                              a_std, a_stf, Uv, dynv, out_x);
    y_kernel<<<76800 / 8, 256>>>(b_out);
    softmax_kernel<<<T_STEPS, 256>>>(out_y);
}

// round 15
// speedup vs baseline: 1.2896x; 1.0337x over previous
#include <cuda_runtime.h>
#include <cuda_fp16.h>
#include <cstdint>

#define T_STEPS 300
#define BATCH   256
#define NIN     128
#define NH      512
#define NOUT    3
#define DTSEC   0.01f
#define ALPHA_N 0.2f

#define Y_SIZE (BATCH * T_STEPS * NOUT)
#define TS_PAD 304

// ---------------- device scratch (static, allocation-free) ----------------
__device__ __half    g_driveh[(size_t)T_STEPS * BATCH * NH];  // 78 MB: 0.2*(inp@Win+b)+noise
__device__ uint32_t  g_wrnnp[(NH / 2) * NH];                  // packed half2 (k-pair x h)
__device__ uint32_t  g_winp[(NIN / 2) * NH];
__device__ float     g_wout[NH * NOUT];
__device__ __half    g_rpost[2 * BATCH * NH];                 // double-buffered activations
__device__ __half    g_xh[(size_t)BATCH * T_STEPS * NH];      // fp16 x_seq copy for y (78 MB)
__device__ float     g_yraw[(size_t)T_STEPS * BATCH * NOUT];
__device__ unsigned  g_flag[16 * 8 * TS_PAD];                 // per (group, slice, step)

// ---------------- prep -----------------------------------------------------
__global__ void prep_kernel(const float* __restrict__ w_in, const float* __restrict__ w_in_mask,
                            const float* __restrict__ w_rnn_base, const float* __restrict__ conn,
                            const float* __restrict__ ei, const float* __restrict__ w_out,
                            const float* __restrict__ w_out_mask)
{
    int tid = blockIdx.x * blockDim.x + threadIdx.x;
    int nth = gridDim.x * blockDim.x;

    for (int i = tid; i < (NH / 2) * NH; i += nth) {
        int p = i >> 9, h = i & (NH - 1);
        int k0 = 2 * p, k1 = 2 * p + 1;
        float s0 = ei[k0 * NH + k0];
        float s1 = ei[k1 * NH + k1];
        float v0 = fmaxf(w_rnn_base[k0 * NH + h] * conn[k0 * NH + h], 0.f) * s0;
        float v1 = fmaxf(w_rnn_base[k1 * NH + h] * conn[k1 * NH + h], 0.f) * s1;
        __half2 hv = __floats2half2_rn(v0, v1);
        g_wrnnp[i] = *reinterpret_cast<uint32_t*>(&hv);
    }
    for (int i = tid; i < (NIN / 2) * NH; i += nth) {
        int p = i >> 9, h = i & (NH - 1);
        float v0 = w_in[(2 * p) * NH + h] * w_in_mask[(2 * p) * NH + h];
        float v1 = w_in[(2 * p + 1) * NH + h] * w_in_mask[(2 * p + 1) * NH + h];
        __half2 hv = __floats2half2_rn(v0, v1);
        g_winp[i] = *reinterpret_cast<uint32_t*>(&hv);
    }
    for (int i = tid; i < NH * NOUT; i += nth)
        g_wout[i] = fmaxf(w_out[i] * w_out_mask[i], 0.f);
    for (int i = tid; i < 16 * 8 * TS_PAD; i += nth)
        g_flag[i] = 0u;
}

// ------- drive GEMM: drive'' = fp16(0.2*(inp@w_in_eff + b_rnn) + noise) ----
__global__ void __launch_bounds__(256) drive_gemm(const float* __restrict__ inp,
                                                  const float* __restrict__ noise,
                                                  const float* __restrict__ b_rnn)
{
    __shared__ __half   a_s[64 * 136];
    __shared__ uint32_t b_s[64 * 68];

    int row0 = blockIdx.x * 64;
    int n0   = blockIdx.y * 64;
    int tid  = threadIdx.x;

    #pragma unroll
    for (int j = 0; j < 32; j++) {
        int idx = tid + j * 256;
        int i = idx >> 7, k = idx & 127;
        a_s[i * 136 + k] = __float2half_rn(inp[(size_t)(row0 + i) * NIN + k]);
    }
    #pragma unroll
    for (int j = 0; j < 16; j++) {
        int idx = tid + j * 256;
        int p = idx >> 6, c = idx & 63;
        b_s[p * 68 + c] = g_winp[p * NH + n0 + c];
    }
    __syncthreads();

    int w = tid >> 5, lane = tid & 31;
    int g = lane >> 2, t = lane & 3;
    int m0 = (w & 3) * 16;
    int nw = (w >> 2) * 32;

    float acc[4][4] = {};
    #pragma unroll
    for (int kk = 0; kk < 8; kk++) {
        int k0 = kk * 16;
        uint32_t a0 = *reinterpret_cast<const uint32_t*>(&a_s[(m0 + g) * 136 + k0 + 2 * t]);
        uint32_t a1 = *reinterpret_cast<const uint32_t*>(&a_s[(m0 + g + 8) * 136 + k0 + 2 * t]);
        uint32_t a2 = *reinterpret_cast<const uint32_t*>(&a_s[(m0 + g) * 136 + k0 + 8 + 2 * t]);
        uint32_t a3 = *reinterpret_cast<const uint32_t*>(&a_s[(m0 + g + 8) * 136 + k0 + 8 + 2 * t]);
        #pragma unroll
        for (int s = 0; s < 4; s++) {
            int col = nw + 8 * s + g;
            uint32_t b0 = b_s[(kk * 8 + t) * 68 + col];
            uint32_t b1 = b_s[(kk * 8 + t + 4) * 68 + col];
            asm volatile("mma.sync.aligned.m16n8k16.row.col.f32.f16.f16.f32 "
                         "{%0,%1,%2,%3}, {%4,%5,%6,%7}, {%8,%9}, {%0,%1,%2,%3};"
                         : "+f"(acc[s][0]), "+f"(acc[s][1]), "+f"(acc[s][2]), "+f"(acc[s][3])
                         : "r"(a0), "r"(a1), "r"(a2), "r"(a3), "r"(b0), "r"(b1));
        }
    }

    __half2* dh = reinterpret_cast<__half2*>(g_driveh);
    #pragma unroll
    for (int s = 0; s < 4; s++) {
        int gc  = n0 + nw + 8 * s + 2 * t;
        float br0 = b_rnn[gc], br1 = b_rnn[gc + 1];
        int r0 = row0 + m0 + g;
        int r1 = r0 + 8;
        float2 nz0 = *reinterpret_cast<const float2*>(&noise[(size_t)r0 * NH + gc]);
        float2 nz1 = *reinterpret_cast<const float2*>(&noise[(size_t)r1 * NH + gc]);
        dh[((size_t)r0 * NH + gc) >> 1] =
            __floats2half2_rn(ALPHA_N * (acc[s][0] + br0) + nz0.x,
                              ALPHA_N * (acc[s][1] + br1) + nz0.y);
        dh[((size_t)r1 * NH + gc) >> 1] =
            __floats2half2_rn(ALPHA_N * (acc[s][2] + br0) + nz1.x,
                              ALPHA_N * (acc[s][3] + br1) + nz1.y);
    }
}

// ---------------- persistent step kernel (R11 layout) -----------------------
// 128 CTAs = 16 b-groups x 8 h-slices. K-split per warp: warp w computes
// partial C over k-range [64w, 64w+64) (= slice w, whose flag it polls),
// loading A-fragments DIRECTLY from L2 into registers. Flat smem reduction
// combines the 8 k-partials. Drive stream is fp16 (78 MB total).
__global__ void __launch_bounds__(256, 1) step_kernel(
    const float* __restrict__ x_init, const float* __restrict__ sx_init,
    const float* __restrict__ su_init,
    const float* __restrict__ a_std, const float* __restrict__ a_stf,
    const float* __restrict__ Uv, const float* __restrict__ dynv,
    float* __restrict__ out_x)
{
    __shared__ float red[8][16][72];     // per-warp partial C, padded rows

    int cta   = blockIdx.x;
    int grp   = cta >> 3;
    int slice = cta & 7;
    int b0 = grp * 16;
    int h0 = slice * 64;
    int tid = threadIdx.x;
    int w = tid >> 5, lane = tid & 31;
    int g = lane >> 2, t = lane & 3;

    // ---- persistent B fragments: warp w's k-range x this CTA's 64 cols ----
    uint32_t breg0[32], breg1[32];
    #pragma unroll
    for (int kk = 0; kk < 4; kk++)
        #pragma unroll
        for (int j = 0; j < 8; j++) {
            int col = h0 + 8 * j + g;
            breg0[kk * 8 + j] = g_wrnnp[(size_t)(32 * w + 8 * kk + t) * NH + col];
            breg1[kk * 8 + j] = g_wrnnp[(size_t)(32 * w + 8 * kk + t + 4) * NH + col];
        }

    int hb  = h0 + 8 * w + 2 * t;
    int br0 = b0 + g, br1 = b0 + g + 8;

    float as0 = a_std[hb], as1 = a_std[hb + 1];
    float af0 = a_stf[hb], af1 = a_stf[hb + 1];
    float U0  = Uv[hb],    U1  = Uv[hb + 1];
    float dy0 = dynv[hb],  dy1 = dynv[hb + 1];

    float x0 = x_init[br0 * NH + hb],   x1 = x_init[br0 * NH + hb + 1];
    float x2 = x_init[br1 * NH + hb],   x3 = x_init[br1 * NH + hb + 1];
    float sx0 = sx_init[br0 * NH + hb], sx1 = sx_init[br0 * NH + hb + 1];
    float sx2 = sx_init[br1 * NH + hb], sx3 = sx_init[br1 * NH + hb + 1];
    float su0 = su_init[br0 * NH + hb], su1 = su_init[br0 * NH + hb + 1];
    float su2 = su_init[br1 * NH + hb], su3 = su_init[br1 * NH + hb + 1];

    __half2* rgl = reinterpret_cast<__half2*>(g_rpost);
    __half2* xh2 = reinterpret_cast<__half2*>(g_xh);
    const __half2* dh = reinterpret_cast<const __half2*>(g_driveh);

    unsigned* my_flag   = g_flag + (grp * 8 + slice) * TS_PAD;   // producer stream
    unsigned* poll_flag = g_flag + (grp * 8 + w) * TS_PAD;       // warp w consumes slice w

    for (int ts = 0; ts < T_STEPS; ts++) {
        // ---- prefetch drive'' (fp16, single load per row pair) ----
        size_t dbase0 = ((size_t)ts * BATCH + br0) * NH + hb;
        size_t dbase1 = ((size_t)ts * BATCH + br1) * NH + hb;
        __half2 dr0 = dh[dbase0 >> 1];
        __half2 dr1 = dh[dbase1 >> 1];

        // ---- phase 1: STP update + x_post + rpost ----
        float xp0, xp1, xp2, xp3;
        {
            float r, sxn, sun;
            r = fmaxf(x0, 0.f);
            sxn = sx0 + (as0 * (1.f - sx0) - DTSEC * su0 * sx0 * r) * dy0;
            sun = su0 + (af0 * (U0 - su0) + DTSEC * U0 * (1.f - su0) * r) * dy0;
            sx0 = fminf(fmaxf(sxn, 0.f), 1.f); su0 = fminf(fmaxf(sun, 0.f), 1.f);
            xp0 = su0 * sx0 * x0;

            r = fmaxf(x1, 0.f);
            sxn = sx1 + (as1 * (1.f - sx1) - DTSEC * su1 * sx1 * r) * dy1;
            sun = su1 + (af1 * (U1 - su1) + DTSEC * U1 * (1.f - su1) * r) * dy1;
            sx1 = fminf(fmaxf(sxn, 0.f), 1.f); su1 = fminf(fmaxf(sun, 0.f), 1.f);
            xp1 = su1 * sx1 * x1;

            r = fmaxf(x2, 0.f);
            sxn = sx2 + (as0 * (1.f - sx2) - DTSEC * su2 * sx2 * r) * dy0;
            sun = su2 + (af0 * (U0 - su2) + DTSEC * U0 * (1.f - su2) * r) * dy0;
            sx2 = fminf(fmaxf(sxn, 0.f), 1.f); su2 = fminf(fmaxf(sun, 0.f), 1.f);
            xp2 = su2 * sx2 * x2;

            r = fmaxf(x3, 0.f);
            sxn = sx3 + (as1 * (1.f - sx3) - DTSEC * su3 * sx3 * r) * dy1;
            sun = su3 + (af1 * (U1 - su3) + DTSEC * U1 * (1.f - su3) * r) * dy1;
            sx3 = fminf(fmaxf(sxn, 0.f), 1.f); su3 = fminf(fmaxf(sun, 0.f), 1.f);
            xp3 = su3 * sx3 * x3;
        }
        int buf = ts & 1;
        rgl[(buf * BATCH * NH + br0 * NH + hb) >> 1] =
            __floats2half2_rn(fmaxf(xp0, 0.f), fmaxf(xp1, 0.f));
        rgl[(buf * BATCH * NH + br1 * NH + hb) >> 1] =
            __floats2half2_rn(fmaxf(xp2, 0.f), fmaxf(xp3, 0.f));

        // ---- publish: single-writer release flag (no RMW) ----
        // Sync also guards red[] reuse (prev step's reduce loads done).
        __syncthreads();
        if (tid == 0)
            asm volatile("st.release.gpu.global.u32 [%0], %1;"
                         :: "l"(my_flag + ts), "r"(1u) : "memory");

        // ---- per-warp: wait for slice w, pull A-fragments to registers ----
        if (w != slice && lane == 0) {
            unsigned v;
            do {
                asm volatile("ld.acquire.gpu.global.u32 %0, [%1];"
                             : "=r"(v) : "l"(poll_flag + ts) : "memory");
            } while (!v);
        }
        __syncwarp();

        uint32_t af[16];
        {
            const __half* Ap = g_rpost + (size_t)buf * BATCH * NH
                               + (size_t)(b0 + g) * NH + 64 * w + 2 * t;
            #pragma unroll
            for (int kk = 0; kk < 4; kk++) {
                asm volatile("ld.global.cg.b32 %0, [%1];"
                             : "=r"(af[kk * 4 + 0]) : "l"(Ap + 16 * kk));
                asm volatile("ld.global.cg.b32 %0, [%1];"
                             : "=r"(af[kk * 4 + 1]) : "l"(Ap + 8 * NH + 16 * kk));
                asm volatile("ld.global.cg.b32 %0, [%1];"
                             : "=r"(af[kk * 4 + 2]) : "l"(Ap + 16 * kk + 8));
                asm volatile("ld.global.cg.b32 %0, [%1];"
                             : "=r"(af[kk * 4 + 3]) : "l"(Ap + 8 * NH + 16 * kk + 8));
            }
        }

        // ---- partial mma: C_w[16x64] = rpost[16, k-slice w] @ W[k-slice w, :]
        float acc[8][4] = {};
        #pragma unroll
        for (int kk = 0; kk < 4; kk++)
            #pragma unroll
            for (int j = 0; j < 8; j++)
                asm volatile("mma.sync.aligned.m16n8k16.row.col.f32.f16.f16.f32 "
                             "{%0,%1,%2,%3}, {%4,%5,%6,%7}, {%8,%9}, {%0,%1,%2,%3};"
                             : "+f"(acc[j][0]), "+f"(acc[j][1]), "+f"(acc[j][2]), "+f"(acc[j][3])
                             : "r"(af[kk * 4 + 0]), "r"(af[kk * 4 + 1]),
                               "r"(af[kk * 4 + 2]), "r"(af[kk * 4 + 3]),
                               "r"(breg0[kk * 8 + j]), "r"(breg1[kk * 8 + j]));

        // ---- store partials to smem ----
        #pragma unroll
        for (int j = 0; j < 8; j++) {
            *reinterpret_cast<float2*>(&red[w][g][8 * j + 2 * t]) =
                make_float2(acc[j][0], acc[j][1]);
            *reinterpret_cast<float2*>(&red[w][g + 8][8 * j + 2 * t]) =
                make_float2(acc[j][2], acc[j][3]);
        }
        __syncthreads();

        // ---- reduce: each thread sums its 4 owned outputs over 8 partials ----
        float s0 = 0.f, s1 = 0.f, s2 = 0.f, s3 = 0.f;
        #pragma unroll
        for (int u = 0; u < 8; u++) {
            float2 p = *reinterpret_cast<const float2*>(&red[u][g][8 * w + 2 * t]);
            float2 q = *reinterpret_cast<const float2*>(&red[u][g + 8][8 * w + 2 * t]);
            s0 += p.x; s1 += p.y; s2 += q.x; s3 += q.y;
        }

        // ---- epilogue: x_new = 0.8*x_post + 0.2*acc + drive'' ----
        float2 dv0 = __half22float2(dr0);
        float2 dv1 = __half22float2(dr1);
        x0 = (1.f - ALPHA_N) * xp0 + ALPHA_N * s0 + dv0.x;
        x1 = (1.f - ALPHA_N) * xp1 + ALPHA_N * s1 + dv0.y;
        x2 = (1.f - ALPHA_N) * xp2 + ALPHA_N * s2 + dv1.x;
        x3 = (1.f - ALPHA_N) * xp3 + ALPHA_N * s3 + dv1.y;
        size_t o0 = ((size_t)br0 * T_STEPS + ts) * NH + hb;
        size_t o1 = ((size_t)br1 * T_STEPS + ts) * NH + hb;
        *reinterpret_cast<float2*>(&out_x[o0]) = make_float2(x0, x1);
        *reinterpret_cast<float2*>(&out_x[o1]) = make_float2(x2, x3);
        xh2[o0 >> 1] = __floats2half2_rn(x0, x1);
        xh2[o1 >> 1] = __floats2half2_rn(x2, x3);
    }
}

// ---------------- y = relu(x) @ w_out_eff + b_out (fp16 input) -------------
__global__ void __launch_bounds__(256) y_kernel(const float* __restrict__ b_out)
{
    __shared__ float wsh[NH * NOUT];
    for (int i = threadIdx.x; i < NH * NOUT; i += 256) wsh[i] = g_wout[i];
    __syncthreads();

    int w = threadIdx.x >> 5, lane = threadIdx.x & 31;
    int row = blockIdx.x * 8 + w;           // t*256 + b
    int t = row >> 8;
    int b = row & 255;
    const __half2* xr = reinterpret_cast<const __half2*>(g_xh)
                        + ((((size_t)b * T_STEPS + t) * NH) >> 1);

    float a0 = 0.f, a1 = 0.f, a2 = 0.f;
    #pragma unroll
    for (int k = 0; k < 8; k++) {
        __half2 hv = xr[lane + 32 * k];
        float2 rf = __half22float2(hv);
        float r0 = fmaxf(rf.x, 0.f), r1 = fmaxf(rf.y, 0.f);
        int h = 2 * (lane + 32 * k);
        a0 += r0 * wsh[h * 3 + 0] + r1 * wsh[h * 3 + 3];
        a1 += r0 * wsh[h * 3 + 1] + r1 * wsh[h * 3 + 4];
        a2 += r0 * wsh[h * 3 + 2] + r1 * wsh[h * 3 + 5];
    }
    #pragma unroll
    for (int off = 16; off > 0; off >>= 1) {
        a0 += __shfl_xor_sync(0xffffffffu, a0, off);
        a1 += __shfl_xor_sync(0xffffffffu, a1, off);
        a2 += __shfl_xor_sync(0xffffffffu, a2, off);
    }
    if (lane == 0) {
        size_t base = ((size_t)t * BATCH + b) * NOUT;
        g_yraw[base + 0] = a0 + b_out[0];
        g_yraw[base + 1] = a1 + b_out[1];
        g_yraw[base + 2] = a2 + b_out[2];
    }
}

// ---------------- softmax over batch axis ----------------------------------
__global__ void __launch_bounds__(256) softmax_kernel(float* __restrict__ out_y)
{
    __shared__ float red[256];
    int t = blockIdx.x;
    int b = threadIdx.x;
    float v[NOUT], e[NOUT];
    #pragma unroll
    for (int o = 0; o < NOUT; o++)
        v[o] = g_yraw[((size_t)t * BATCH + b) * NOUT + o];

    #pragma unroll
    for (int o = 0; o < NOUT; o++) {
        red[b] = v[o];
        __syncthreads();
        for (int s = 128; s > 0; s >>= 1) {
            if (b < s) red[b] = fmaxf(red[b], red[b + s]);
            __syncthreads();
        }
        float mx = red[0];
        __syncthreads();
        e[o] = expf(v[o] - mx);
        red[b] = e[o];
        __syncthreads();
        for (int s = 128; s > 0; s >>= 1) {
            if (b < s) red[b] += red[b + s];
            __syncthreads();
        }
        float sm = red[0];
        __syncthreads();
        out_y[((size_t)b * T_STEPS + t) * NOUT + o] = e[o] / sm;
    }
}

// ---------------- launch ----------------------------------------------------
extern "C" void kernel_launch(void* const* d_in, const int* in_sizes, int n_in,
                              void* d_out, int out_size)
{
    const float* input_data = (const float*)d_in[0];
    const float* noise      = (const float*)d_in[1];
    const float* x_init     = (const float*)d_in[2];
    const float* syn_x_init = (const float*)d_in[3];
    const float* syn_u_init = (const float*)d_in[4];
    const float* w_in       = (const float*)d_in[5];
    const float* w_in_mask  = (const float*)d_in[6];
    const float* w_rnn_base = (const float*)d_in[7];
    const float* conn_mask  = (const float*)d_in[8];
    const float* ei_matrix  = (const float*)d_in[9];
    const float* b_rnn      = (const float*)d_in[10];
    const float* w_out      = (const float*)d_in[11];
    const float* w_out_mask = (const float*)d_in[12];
    const float* b_out      = (const float*)d_in[13];
    const float* a_std      = (const float*)d_in[14];
    const float* a_stf      = (const float*)d_in[15];
    const float* Uv         = (const float*)d_in[16];
    const float* dynv       = (const float*)d_in[17];

    float* out   = (float*)d_out;
    float* out_y = out;
    float* out_x = out + Y_SIZE;

    prep_kernel<<<148, 256>>>(w_in, w_in_mask, w_rnn_base, conn_mask, ei_matrix,
                              w_out, w_out_mask);
    dim3 dgrid(76800 / 64, NH / 64);
    drive_gemm<<<dgrid, 256>>>(input_data, noise, b_rnn);
    step_kernel<<<128, 256>>>(x_init, syn_x_init, syn_u_init,
                              a_std, a_stf, Uv, dynv, out_x);
    y_kernel<<<76800 / 8, 256>>>(b_out);
    softmax_kernel<<<T_STEPS, 256>>>(out_y);
}

// round 16
// speedup vs baseline: 1.2957x; 1.0048x over previous
#include <cuda_runtime.h>
#include <cuda_fp16.h>
#include <cstdint>

#define T_STEPS 300
#define BATCH   256
#define NIN     128
#define NH      512
#define NOUT    3
#define DTSEC   0.01f
#define ALPHA_N 0.2f

#define Y_SIZE (BATCH * T_STEPS * NOUT)
#define TS_PAD 304

// ---------------- device scratch (static, allocation-free) ----------------
__device__ __half    g_driveh[(size_t)T_STEPS * BATCH * NH];  // 78 MB: 0.2*(inp@Win+b)+noise
__device__ uint32_t  g_wrnnp[(NH / 2) * NH];                  // packed half2 (k-pair x h)
__device__ uint32_t  g_winp[(NIN / 2) * NH];
__device__ float     g_wout[NH * NOUT];
__device__ __half    g_rpost[2 * BATCH * NH];                 // double-buffered activations
__device__ __half    g_xh[(size_t)BATCH * T_STEPS * NH];      // fp16 x_seq copy for y (78 MB)
__device__ float     g_yraw[(size_t)T_STEPS * BATCH * NOUT];
__device__ unsigned  g_flag[16 * 8 * TS_PAD];                 // per (group, slice, step)

// ---------------- prep -----------------------------------------------------
__global__ void prep_kernel(const float* __restrict__ w_in, const float* __restrict__ w_in_mask,
                            const float* __restrict__ w_rnn_base, const float* __restrict__ conn,
                            const float* __restrict__ ei, const float* __restrict__ w_out,
                            const float* __restrict__ w_out_mask)
{
    int tid = blockIdx.x * blockDim.x + threadIdx.x;
    int nth = gridDim.x * blockDim.x;

    for (int i = tid; i < (NH / 2) * NH; i += nth) {
        int p = i >> 9, h = i & (NH - 1);
        int k0 = 2 * p, k1 = 2 * p + 1;
        float s0 = ei[k0 * NH + k0];
        float s1 = ei[k1 * NH + k1];
        float v0 = fmaxf(w_rnn_base[k0 * NH + h] * conn[k0 * NH + h], 0.f) * s0;
        float v1 = fmaxf(w_rnn_base[k1 * NH + h] * conn[k1 * NH + h], 0.f) * s1;
        __half2 hv = __floats2half2_rn(v0, v1);
        g_wrnnp[i] = *reinterpret_cast<uint32_t*>(&hv);
    }
    for (int i = tid; i < (NIN / 2) * NH; i += nth) {
        int p = i >> 9, h = i & (NH - 1);
        float v0 = w_in[(2 * p) * NH + h] * w_in_mask[(2 * p) * NH + h];
        float v1 = w_in[(2 * p + 1) * NH + h] * w_in_mask[(2 * p + 1) * NH + h];
        __half2 hv = __floats2half2_rn(v0, v1);
        g_winp[i] = *reinterpret_cast<uint32_t*>(&hv);
    }
    for (int i = tid; i < NH * NOUT; i += nth)
        g_wout[i] = fmaxf(w_out[i] * w_out_mask[i], 0.f);
    for (int i = tid; i < 16 * 8 * TS_PAD; i += nth)
        g_flag[i] = 0u;
}

// ------- drive GEMM: drive'' = fp16(0.2*(inp@w_in_eff + b_rnn) + noise) ----
__global__ void __launch_bounds__(256) drive_gemm(const float* __restrict__ inp,
                                                  const float* __restrict__ noise,
                                                  const float* __restrict__ b_rnn)
{
    __shared__ __half   a_s[64 * 136];
    __shared__ uint32_t b_s[64 * 68];

    int row0 = blockIdx.x * 64;
    int n0   = blockIdx.y * 64;
    int tid  = threadIdx.x;

    #pragma unroll
    for (int j = 0; j < 32; j++) {
        int idx = tid + j * 256;
        int i = idx >> 7, k = idx & 127;
        a_s[i * 136 + k] = __float2half_rn(inp[(size_t)(row0 + i) * NIN + k]);
    }
    #pragma unroll
    for (int j = 0; j < 16; j++) {
        int idx = tid + j * 256;
        int p = idx >> 6, c = idx & 63;
        b_s[p * 68 + c] = g_winp[p * NH + n0 + c];
    }
    __syncthreads();

    int w = tid >> 5, lane = tid & 31;
    int g = lane >> 2, t = lane & 3;
    int m0 = (w & 3) * 16;
    int nw = (w >> 2) * 32;

    float acc[4][4] = {};
    #pragma unroll
    for (int kk = 0; kk < 8; kk++) {
        int k0 = kk * 16;
        uint32_t a0 = *reinterpret_cast<const uint32_t*>(&a_s[(m0 + g) * 136 + k0 + 2 * t]);
        uint32_t a1 = *reinterpret_cast<const uint32_t*>(&a_s[(m0 + g + 8) * 136 + k0 + 2 * t]);
        uint32_t a2 = *reinterpret_cast<const uint32_t*>(&a_s[(m0 + g) * 136 + k0 + 8 + 2 * t]);
        uint32_t a3 = *reinterpret_cast<const uint32_t*>(&a_s[(m0 + g + 8) * 136 + k0 + 8 + 2 * t]);
        #pragma unroll
        for (int s = 0; s < 4; s++) {
            int col = nw + 8 * s + g;
            uint32_t b0 = b_s[(kk * 8 + t) * 68 + col];
            uint32_t b1 = b_s[(kk * 8 + t + 4) * 68 + col];
            asm volatile("mma.sync.aligned.m16n8k16.row.col.f32.f16.f16.f32 "
                         "{%0,%1,%2,%3}, {%4,%5,%6,%7}, {%8,%9}, {%0,%1,%2,%3};"
                         : "+f"(acc[s][0]), "+f"(acc[s][1]), "+f"(acc[s][2]), "+f"(acc[s][3])
                         : "r"(a0), "r"(a1), "r"(a2), "r"(a3), "r"(b0), "r"(b1));
        }
    }

    __half2* dh = reinterpret_cast<__half2*>(g_driveh);
    #pragma unroll
    for (int s = 0; s < 4; s++) {
        int gc  = n0 + nw + 8 * s + 2 * t;
        float br0 = b_rnn[gc], br1 = b_rnn[gc + 1];
        int r0 = row0 + m0 + g;
        int r1 = r0 + 8;
        float2 nz0 = *reinterpret_cast<const float2*>(&noise[(size_t)r0 * NH + gc]);
        float2 nz1 = *reinterpret_cast<const float2*>(&noise[(size_t)r1 * NH + gc]);
        dh[((size_t)r0 * NH + gc) >> 1] =
            __floats2half2_rn(ALPHA_N * (acc[s][0] + br0) + nz0.x,
                              ALPHA_N * (acc[s][1] + br1) + nz0.y);
        dh[((size_t)r1 * NH + gc) >> 1] =
            __floats2half2_rn(ALPHA_N * (acc[s][2] + br0) + nz1.x,
                              ALPHA_N * (acc[s][3] + br1) + nz1.y);
    }
}

// ---------------- persistent step kernel (R11/R15 layout, UNCHANGED) -------
// 128 CTAs = 16 b-groups x 8 h-slices. K-split per warp: warp w computes
// partial C over k-range [64w, 64w+64) (= slice w, whose flag it polls),
// loading A-fragments DIRECTLY from L2 into registers. Flat smem reduction
// combines the 8 k-partials. Drive stream is fp16 (78 MB total).
__global__ void __launch_bounds__(256, 1) step_kernel(
    const float* __restrict__ x_init, const float* __restrict__ sx_init,
    const float* __restrict__ su_init,
    const float* __restrict__ a_std, const float* __restrict__ a_stf,
    const float* __restrict__ Uv, const float* __restrict__ dynv,
    float* __restrict__ out_x)
{
    __shared__ float red[8][16][72];     // per-warp partial C, padded rows

    int cta   = blockIdx.x;
    int grp   = cta >> 3;
    int slice = cta & 7;
    int b0 = grp * 16;
    int h0 = slice * 64;
    int tid = threadIdx.x;
    int w = tid >> 5, lane = tid & 31;
    int g = lane >> 2, t = lane & 3;

    // ---- persistent B fragments: warp w's k-range x this CTA's 64 cols ----
    uint32_t breg0[32], breg1[32];
    #pragma unroll
    for (int kk = 0; kk < 4; kk++)
        #pragma unroll
        for (int j = 0; j < 8; j++) {
            int col = h0 + 8 * j + g;
            breg0[kk * 8 + j] = g_wrnnp[(size_t)(32 * w + 8 * kk + t) * NH + col];
            breg1[kk * 8 + j] = g_wrnnp[(size_t)(32 * w + 8 * kk + t + 4) * NH + col];
        }

    int hb  = h0 + 8 * w + 2 * t;
    int br0 = b0 + g, br1 = b0 + g + 8;

    float as0 = a_std[hb], as1 = a_std[hb + 1];
    float af0 = a_stf[hb], af1 = a_stf[hb + 1];
    float U0  = Uv[hb],    U1  = Uv[hb + 1];
    float dy0 = dynv[hb],  dy1 = dynv[hb + 1];

    float x0 = x_init[br0 * NH + hb],   x1 = x_init[br0 * NH + hb + 1];
    float x2 = x_init[br1 * NH + hb],   x3 = x_init[br1 * NH + hb + 1];
    float sx0 = sx_init[br0 * NH + hb], sx1 = sx_init[br0 * NH + hb + 1];
    float sx2 = sx_init[br1 * NH + hb], sx3 = sx_init[br1 * NH + hb + 1];
    float su0 = su_init[br0 * NH + hb], su1 = su_init[br0 * NH + hb + 1];
    float su2 = su_init[br1 * NH + hb], su3 = su_init[br1 * NH + hb + 1];

    __half2* rgl = reinterpret_cast<__half2*>(g_rpost);
    __half2* xh2 = reinterpret_cast<__half2*>(g_xh);
    const __half2* dh = reinterpret_cast<const __half2*>(g_driveh);

    unsigned* my_flag   = g_flag + (grp * 8 + slice) * TS_PAD;   // producer stream
    unsigned* poll_flag = g_flag + (grp * 8 + w) * TS_PAD;       // warp w consumes slice w

    for (int ts = 0; ts < T_STEPS; ts++) {
        // ---- prefetch drive'' (fp16, single load per row pair) ----
        size_t dbase0 = ((size_t)ts * BATCH + br0) * NH + hb;
        size_t dbase1 = ((size_t)ts * BATCH + br1) * NH + hb;
        __half2 dr0 = dh[dbase0 >> 1];
        __half2 dr1 = dh[dbase1 >> 1];

        // ---- phase 1: STP update + x_post + rpost ----
        float xp0, xp1, xp2, xp3;
        {
            float r, sxn, sun;
            r = fmaxf(x0, 0.f);
            sxn = sx0 + (as0 * (1.f - sx0) - DTSEC * su0 * sx0 * r) * dy0;
            sun = su0 + (af0 * (U0 - su0) + DTSEC * U0 * (1.f - su0) * r) * dy0;
            sx0 = fminf(fmaxf(sxn, 0.f), 1.f); su0 = fminf(fmaxf(sun, 0.f), 1.f);
            xp0 = su0 * sx0 * x0;

            r = fmaxf(x1, 0.f);
            sxn = sx1 + (as1 * (1.f - sx1) - DTSEC * su1 * sx1 * r) * dy1;
            sun = su1 + (af1 * (U1 - su1) + DTSEC * U1 * (1.f - su1) * r) * dy1;
            sx1 = fminf(fmaxf(sxn, 0.f), 1.f); su1 = fminf(fmaxf(sun, 0.f), 1.f);
            xp1 = su1 * sx1 * x1;

            r = fmaxf(x2, 0.f);
            sxn = sx2 + (as0 * (1.f - sx2) - DTSEC * su2 * sx2 * r) * dy0;
            sun = su2 + (af0 * (U0 - su2) + DTSEC * U0 * (1.f - su2) * r) * dy0;
            sx2 = fminf(fmaxf(sxn, 0.f), 1.f); su2 = fminf(fmaxf(sun, 0.f), 1.f);
            xp2 = su2 * sx2 * x2;

            r = fmaxf(x3, 0.f);
            sxn = sx3 + (as1 * (1.f - sx3) - DTSEC * su3 * sx3 * r) * dy1;
            sun = su3 + (af1 * (U1 - su3) + DTSEC * U1 * (1.f - su3) * r) * dy1;
            sx3 = fminf(fmaxf(sxn, 0.f), 1.f); su3 = fminf(fmaxf(sun, 0.f), 1.f);
            xp3 = su3 * sx3 * x3;
        }
        int buf = ts & 1;
        rgl[(buf * BATCH * NH + br0 * NH + hb) >> 1] =
            __floats2half2_rn(fmaxf(xp0, 0.f), fmaxf(xp1, 0.f));
        rgl[(buf * BATCH * NH + br1 * NH + hb) >> 1] =
            __floats2half2_rn(fmaxf(xp2, 0.f), fmaxf(xp3, 0.f));

        // ---- publish: single-writer release flag (no RMW) ----
        // Sync also guards red[] reuse (prev step's reduce loads done).
        __syncthreads();
        if (tid == 0)
            asm volatile("st.release.gpu.global.u32 [%0], %1;"
                         :: "l"(my_flag + ts), "r"(1u) : "memory");

        // ---- per-warp: wait for slice w, pull A-fragments to registers ----
        if (w != slice && lane == 0) {
            unsigned v;
            do {
                asm volatile("ld.acquire.gpu.global.u32 %0, [%1];"
                             : "=r"(v) : "l"(poll_flag + ts) : "memory");
            } while (!v);
        }
        __syncwarp();

        uint32_t af[16];
        {
            const __half* Ap = g_rpost + (size_t)buf * BATCH * NH
                               + (size_t)(b0 + g) * NH + 64 * w + 2 * t;
            #pragma unroll
            for (int kk = 0; kk < 4; kk++) {
                asm volatile("ld.global.cg.b32 %0, [%1];"
                             : "=r"(af[kk * 4 + 0]) : "l"(Ap + 16 * kk));
                asm volatile("ld.global.cg.b32 %0, [%1];"
                             : "=r"(af[kk * 4 + 1]) : "l"(Ap + 8 * NH + 16 * kk));
                asm volatile("ld.global.cg.b32 %0, [%1];"
                             : "=r"(af[kk * 4 + 2]) : "l"(Ap + 16 * kk + 8));
                asm volatile("ld.global.cg.b32 %0, [%1];"
                             : "=r"(af[kk * 4 + 3]) : "l"(Ap + 8 * NH + 16 * kk + 8));
            }
        }

        // ---- partial mma: C_w[16x64] = rpost[16, k-slice w] @ W[k-slice w, :]
        float acc[8][4] = {};
        #pragma unroll
        for (int kk = 0; kk < 4; kk++)
            #pragma unroll
            for (int j = 0; j < 8; j++)
                asm volatile("mma.sync.aligned.m16n8k16.row.col.f32.f16.f16.f32 "
                             "{%0,%1,%2,%3}, {%4,%5,%6,%7}, {%8,%9}, {%0,%1,%2,%3};"
                             : "+f"(acc[j][0]), "+f"(acc[j][1]), "+f"(acc[j][2]), "+f"(acc[j][3])
                             : "r"(af[kk * 4 + 0]), "r"(af[kk * 4 + 1]),
                               "r"(af[kk * 4 + 2]), "r"(af[kk * 4 + 3]),
                               "r"(breg0[kk * 8 + j]), "r"(breg1[kk * 8 + j]));

        // ---- store partials to smem ----
        #pragma unroll
        for (int j = 0; j < 8; j++) {
            *reinterpret_cast<float2*>(&red[w][g][8 * j + 2 * t]) =
                make_float2(acc[j][0], acc[j][1]);
            *reinterpret_cast<float2*>(&red[w][g + 8][8 * j + 2 * t]) =
                make_float2(acc[j][2], acc[j][3]);
        }
        __syncthreads();

        // ---- reduce: each thread sums its 4 owned outputs over 8 partials ----
        float s0 = 0.f, s1 = 0.f, s2 = 0.f, s3 = 0.f;
        #pragma unroll
        for (int u = 0; u < 8; u++) {
            float2 p = *reinterpret_cast<const float2*>(&red[u][g][8 * w + 2 * t]);
            float2 q = *reinterpret_cast<const float2*>(&red[u][g + 8][8 * w + 2 * t]);
            s0 += p.x; s1 += p.y; s2 += q.x; s3 += q.y;
        }

        // ---- epilogue: x_new = 0.8*x_post + 0.2*acc + drive'' ----
        float2 dv0 = __half22float2(dr0);
        float2 dv1 = __half22float2(dr1);
        x0 = (1.f - ALPHA_N) * xp0 + ALPHA_N * s0 + dv0.x;
        x1 = (1.f - ALPHA_N) * xp1 + ALPHA_N * s1 + dv0.y;
        x2 = (1.f - ALPHA_N) * xp2 + ALPHA_N * s2 + dv1.x;
        x3 = (1.f - ALPHA_N) * xp3 + ALPHA_N * s3 + dv1.y;
        size_t o0 = ((size_t)br0 * T_STEPS + ts) * NH + hb;
        size_t o1 = ((size_t)br1 * T_STEPS + ts) * NH + hb;
        *reinterpret_cast<float2*>(&out_x[o0]) = make_float2(x0, x1);
        *reinterpret_cast<float2*>(&out_x[o1]) = make_float2(x2, x3);
        xh2[o0 >> 1] = __floats2half2_rn(x0, x1);
        xh2[o1 >> 1] = __floats2half2_rn(x2, x3);
    }
}

// ---------------- y = relu(x) @ w_out_eff + b_out (fp16 x, half2 weights) --
__global__ void __launch_bounds__(256) y_kernel(const float* __restrict__ b_out)
{
    // wsh2[o][i] = (w_out_eff[2i][o], w_out_eff[2i+1][o]) as half2
    __shared__ __half2 wsh2[3][256];
    for (int idx = threadIdx.x; idx < 3 * 256; idx += 256) {
        int o = idx >> 8, i = idx & 255;
        wsh2[o][i] = __floats2half2_rn(g_wout[(2 * i) * 3 + o],
                                       g_wout[(2 * i + 1) * 3 + o]);
    }
    __syncthreads();

    int w = threadIdx.x >> 5, lane = threadIdx.x & 31;
    int row = blockIdx.x * 8 + w;           // t*256 + b
    int t = row >> 8;
    int b = row & 255;
    const __half2* xr = reinterpret_cast<const __half2*>(g_xh)
                        + ((((size_t)b * T_STEPS + t) * NH) >> 1);

    float a0 = 0.f, a1 = 0.f, a2 = 0.f;
    #pragma unroll
    for (int k = 0; k < 8; k++) {
        int i = lane + 32 * k;
        __half2 hv = xr[i];
        float2 rf = __half22float2(hv);
        float r0 = fmaxf(rf.x, 0.f), r1 = fmaxf(rf.y, 0.f);
        float2 w0 = __half22float2(wsh2[0][i]);
        float2 w1 = __half22float2(wsh2[1][i]);
        float2 w2 = __half22float2(wsh2[2][i]);
        a0 += r0 * w0.x + r1 * w0.y;
        a1 += r0 * w1.x + r1 * w1.y;
        a2 += r0 * w2.x + r1 * w2.y;
    }
    #pragma unroll
    for (int off = 16; off > 0; off >>= 1) {
        a0 += __shfl_xor_sync(0xffffffffu, a0, off);
        a1 += __shfl_xor_sync(0xffffffffu, a1, off);
        a2 += __shfl_xor_sync(0xffffffffu, a2, off);
    }
    if (lane == 0) {
        size_t base = ((size_t)t * BATCH + b) * NOUT;
        g_yraw[base + 0] = a0 + b_out[0];
        g_yraw[base + 1] = a1 + b_out[1];
        g_yraw[base + 2] = a2 + b_out[2];
    }
}

// ---------------- softmax over batch axis ----------------------------------
__global__ void __launch_bounds__(256) softmax_kernel(float* __restrict__ out_y)
{
    __shared__ float red[256];
    int t = blockIdx.x;
    int b = threadIdx.x;
    float v[NOUT], e[NOUT];
    #pragma unroll
    for (int o = 0; o < NOUT; o++)
        v[o] = g_yraw[((size_t)t * BATCH + b) * NOUT + o];

    #pragma unroll
    for (int o = 0; o < NOUT; o++) {
        red[b] = v[o];
        __syncthreads();
        for (int s = 128; s > 0; s >>= 1) {
            if (b < s) red[b] = fmaxf(red[b], red[b + s]);
            __syncthreads();
        }
        float mx = red[0];
        __syncthreads();
        e[o] = expf(v[o] - mx);
        red[b] = e[o];
        __syncthreads();
        for (int s = 128; s > 0; s >>= 1) {
            if (b < s) red[b] += red[b + s];
            __syncthreads();
        }
        float sm = red[0];
        __syncthreads();
        out_y[((size_t)b * T_STEPS + t) * NOUT + o] = e[o] / sm;
    }
}

// ---------------- launch ----------------------------------------------------
extern "C" void kernel_launch(void* const* d_in, const int* in_sizes, int n_in,
                              void* d_out, int out_size)
{
    const float* input_data = (const float*)d_in[0];
    const float* noise      = (const float*)d_in[1];
    const float* x_init     = (const float*)d_in[2];
    const float* syn_x_init = (const float*)d_in[3];
    const float* syn_u_init = (const float*)d_in[4];
    const float* w_in       = (const float*)d_in[5];
    const float* w_in_mask  = (const float*)d_in[6];
    const float* w_rnn_base = (const float*)d_in[7];
    const float* conn_mask  = (const float*)d_in[8];
    const float* ei_matrix  = (const float*)d_in[9];
    const float* b_rnn      = (const float*)d_in[10];
    const float* w_out      = (const float*)d_in[11];
    const float* w_out_mask = (const float*)d_in[12];
    const float* b_out      = (const float*)d_in[13];
    const float* a_std      = (const float*)d_in[14];
    const float* a_stf      = (const float*)d_in[15];
    const float* Uv         = (const float*)d_in[16];
    const float* dynv       = (const float*)d_in[17];

    float* out   = (float*)d_out;
    float* out_y = out;
    float* out_x = out + Y_SIZE;

    prep_kernel<<<592, 256>>>(w_in, w_in_mask, w_rnn_base, conn_mask, ei_matrix,
                              w_out, w_out_mask);
    dim3 dgrid(76800 / 64, NH / 64);
    drive_gemm<<<dgrid, 256>>>(input_data, noise, b_rnn);
    step_kernel<<<128, 256>>>(x_init, syn_x_init, syn_u_init,
                              a_std, a_stf, Uv, dynv, out_x);
    y_kernel<<<76800 / 8, 256>>>(b_out);
    softmax_kernel<<<T_STEPS, 256>>>(out_y);
}